// round 16
// baseline (speedup 1.0000x reference)
#include <cuda_runtime.h>
#include <cuda_bf16.h>
#include <cstdint>

// Embedding gather + sinusoidal positional encoding.
// out[row, c] = W[ids[row], c] + (row even ? sin : cos)(row * freq(c)),
//   freq(c) = 10000^(-2c/D)
//
// D = 1024, TOKENS = 8192. Grid = 1024 CTAs x 8 rows, 512 threads.
// PARALLEL-HALVES variant of the best (R7) shape: warps 0-7 handle rows
// r0+0..3, warps 8-15 handle rows r0+4..7, concurrently (NOT two sequential
// phases — R14's mistake). Per-warp structure identical to R7: front-batched
// 4x LDG.128 (MLP=4), one int4 ids load, Cody-Waite + MUFU sincos prologue,
// rotor recurrence. CTA head (ids -> gather chain) amortized over 8 rows;
// grid halved to 1024.

static constexpr int D       = 1024;
static constexpr int VEC     = 4;
static constexpr int THREADS = 512;
static constexpr int R       = 8;         // rows per CTA (two 4-row halves)

// sincos for 0 <= x <= ~8200: 3-term Cody-Waite reduction mod 2*pi, then MUFU.
__device__ __forceinline__ void fast_sincos(float x, float& s, float& c)
{
    const float INV2PI = 0.15915494309189535f;
    const float C1 = 6.28125f;
    const float C2 = 1.93530717957e-3f;
    const float C3 = 6.1232339957e-10f;
    float q = rintf(x * INV2PI);
    float a = fmaf(-q, C1, x);
    a = fmaf(-q, C2, a);
    a = fmaf(-q, C3, a);
    s = __sinf(a);
    c = __cosf(a);
}

__global__ __launch_bounds__(THREADS, 3)
void emb_pe_kernel(const int* __restrict__ ids,
                   const float* __restrict__ W,
                   float* __restrict__ out)
{
    const int t    = threadIdx.x;             // 0..511
    const int half = t >> 8;                  // 0: rows +0..3, 1: rows +4..7
    const int tloc = t & 255;                 // thread within half
    const int c0   = tloc * VEC;              // starting column

    const int row0 = blockIdx.x * R + half * 4;   // multiple of 4 -> even

    // One 16B load covers this half's 4 ids (aligned since row0 % 4 == 0).
    const int4 ii = *reinterpret_cast<const int4*>(ids + row0);

    const float* Wc = W + c0;

    // Front-batch all 4 gathers (independent LDG.128, MLP=4).
    const float4 v0 = *reinterpret_cast<const float4*>(Wc + (size_t)ii.x * D);
    const float4 v1 = *reinterpret_cast<const float4*>(Wc + (size_t)ii.y * D);
    const float4 v2 = *reinterpret_cast<const float4*>(Wc + (size_t)ii.z * D);
    const float4 v3 = *reinterpret_cast<const float4*>(Wc + (size_t)ii.w * D);

    // freq(c) = 2^(kexp * c),  kexp = -2*log2(10000)/D  (overlaps load latency)
    const float kexp = -13.287712379549449f * 2.0f / (float)D;
    const float pos0 = (float)row0;

    float s[VEC], c[VEC], sd[VEC], cd[VEC];
#pragma unroll
    for (int i = 0; i < VEC; i++) {
        float freq = exp2f(kexp * (float)(c0 + i));
        fast_sincos(pos0 * freq, s[i], c[i]);   // start rotor
        fast_sincos(freq,        sd[i], cd[i]); // +1 row delta rotor
    }

    float* outp = out + (size_t)row0 * D + c0;
    float4 o;

    // row0 (even): + sin
    o.x = v0.x + s[0]; o.y = v0.y + s[1]; o.z = v0.z + s[2]; o.w = v0.w + s[3];
    *reinterpret_cast<float4*>(outp) = o;

#pragma unroll
    for (int i = 0; i < VEC; i++) {           // rotate +1
        float ns = fmaf(s[i], cd[i],  c[i] * sd[i]);
        float nc = fmaf(c[i], cd[i], -s[i] * sd[i]);
        s[i] = ns; c[i] = nc;
    }

    // row0+1 (odd): + cos
    o.x = v1.x + c[0]; o.y = v1.y + c[1]; o.z = v1.z + c[2]; o.w = v1.w + c[3];
    *reinterpret_cast<float4*>(outp + D) = o;

#pragma unroll
    for (int i = 0; i < VEC; i++) {           // rotate +1
        float ns = fmaf(s[i], cd[i],  c[i] * sd[i]);
        float nc = fmaf(c[i], cd[i], -s[i] * sd[i]);
        s[i] = ns; c[i] = nc;
    }

    // row0+2 (even): + sin
    o.x = v2.x + s[0]; o.y = v2.y + s[1]; o.z = v2.z + s[2]; o.w = v2.w + s[3];
    *reinterpret_cast<float4*>(outp + 2 * D) = o;

#pragma unroll
    for (int i = 0; i < VEC; i++) {           // rotate +1
        float ns = fmaf(s[i], cd[i],  c[i] * sd[i]);
        float nc = fmaf(c[i], cd[i], -s[i] * sd[i]);
        s[i] = ns; c[i] = nc;
    }

    // row0+3 (odd): + cos
    o.x = v3.x + c[0]; o.y = v3.y + c[1]; o.z = v3.z + c[2]; o.w = v3.w + c[3];
    *reinterpret_cast<float4*>(outp + 3 * D) = o;
}

extern "C" void kernel_launch(void* const* d_in, const int* in_sizes, int n_in,
                              void* d_out, int out_size)
{
    const int*   ids = (const int*)d_in[0];
    const float* W   = (const float*)d_in[1];
    float*       out = (float*)d_out;

    const int rows = in_sizes[0];             // 8192 tokens
    emb_pe_kernel<<<rows / R, THREADS>>>(ids, W, out);
}